// round 5
// baseline (speedup 1.0000x reference)
#include <cuda_runtime.h>
#include <stdint.h>

// Problem constants: B=16, L=4096, H=768 (fp32)
#define B_ 16
#define L_ 4096
#define H_ 768
#define H4 (H_ / 4)            // 192 float4 lanes per row
#define TOK_PER_BLK 32         // tokens per block tile
#define CH 8                   // rows prefetched per chunk (per-thread MLP)
#define BLOCKS_PER_BATCH (L_ / TOK_PER_BLK)  // 128

__global__ __launch_bounds__(H4)
void token_segment_sum_kernel(const float* __restrict__ x,
                              const int*   __restrict__ seg,
                              float*       __restrict__ out)
{
    const int b    = blockIdx.x / BLOCKS_PER_BATCH;
    const int tile = blockIdx.x % BLOCKS_PER_BATCH;
    const int j0   = tile * TOK_PER_BLK;

    const int* __restrict__ segb = seg + b * L_;

    __shared__ int bnd[TOK_PER_BLK + 1];

    const int t = threadIdx.x;   // 0..191 (float4 lane)
    if (t <= TOK_PER_BLK) {
        // lower_bound: first index i with segb[i] >= (j0 + t)
        const int target = j0 + t;
        int lo = 0, hi = L_;
        #pragma unroll 1
        while (lo < hi) {
            int mid = (lo + hi) >> 1;
            if (segb[mid] < target) lo = mid + 1; else hi = mid;
        }
        bnd[t] = lo;
    }
    __syncthreads();

    const float4* __restrict__ xb =
        reinterpret_cast<const float4*>(x + (size_t)b * L_ * H_);
    float4* __restrict__ ob =
        reinterpret_cast<float4*>(out + (size_t)b * L_ * H_);

    const int s0 = bnd[0];
    const int s1 = bnd[TOK_PER_BLK];

    int j = 0;

    // flush tokens that are empty at the very start (bnd[j+1] == s0)
    // default write-back stores: L2 buffers output, batches DRAM writebacks
    #pragma unroll 1
    while (j < TOK_PER_BLK && bnd[j + 1] == s0) {
        ob[(size_t)(j0 + j) * H4 + t] = make_float4(0.f, 0.f, 0.f, 0.f);
        j++;
    }

    float4 acc = make_float4(0.f, 0.f, 0.f, 0.f);

    // stream contiguous rows [s0, s1) in chunks of CH independent loads.
    // __ldcs: input is read exactly once -> evict-first, keep L2 for writes.
    #pragma unroll 1
    for (int base = s0; base < s1; base += CH) {
        const int n = min(CH, s1 - base);

        float4 v[CH];
        #pragma unroll
        for (int i = 0; i < CH; i++)
            if (i < n)
                v[i] = __ldcs(&xb[(size_t)(base + i) * H4 + t]);

        #pragma unroll
        for (int i = 0; i < CH; i++) {
            if (i < n) {
                acc.x += v[i].x; acc.y += v[i].y;
                acc.z += v[i].z; acc.w += v[i].w;
                const int pos1 = base + i + 1;
                // flush every token ending exactly here (empty tokens store
                // zero since acc resets between equal boundaries)
                #pragma unroll 1
                while (j < TOK_PER_BLK && bnd[j + 1] == pos1) {
                    ob[(size_t)(j0 + j) * H4 + t] = acc;
                    acc = make_float4(0.f, 0.f, 0.f, 0.f);
                    j++;
                }
            }
        }
    }
}

extern "C" void kernel_launch(void* const* d_in, const int* in_sizes, int n_in,
                              void* d_out, int out_size)
{
    const float* x   = (const float*)d_in[0];   // sequence_output  [B, L, H] f32
    const int*   seg = (const int*)  d_in[1];   // wordpiece_to_token [B, L] i32
    float*       out = (float*)d_out;           // [B, L, H] f32

    dim3 grid(B_ * BLOCKS_PER_BATCH);           // 2048 blocks
    dim3 block(H4);                             // 192 threads
    token_segment_sum_kernel<<<grid, block>>>(x, seg, out);
}